// round 9
// baseline (speedup 1.0000x reference)
#include <cuda_runtime.h>
#include <cuda_bf16.h>
#include <math.h>
#include <stdint.h>

#define NCLS 80
#define BB   32
#define TT   64
#define HW4  (80*80)
#define HW5  (40*40)
#define NT   (BB*TT)          // 2048 targets per scale; 4096 total
#define GRID 1024             // 4 targets per block, 2 warps per target
#define BLK  256
#define N4Q  (BB*HW4/4)       // 51200 float4 quads, scale 4
#define N5Q  (BB*HW5/4)       // 12800 quads, scale 5

// ---- persistent device scratch (zero at load; epoch scheme avoids cleanup) ----
__device__ uint32_t g_map4[BB*HW4];
__device__ uint32_t g_map5[BB*HW5];
// 0 lb, 1 lo, 2 lc, 3 n, 4 tot4, 5 tot5, 6 corr4, 7 corr5
__device__ float    g_accf[8];
__device__ int      g_hit[2];
__device__ unsigned g_done;
__device__ uint32_t g_epoch;

__device__ __forceinline__ float softplus_fast(float x) {
    float em = __expf(-fabsf(x));
    return fmaxf(x, 0.f) + __logf(1.f + em);
}

__device__ __forceinline__ float focal1(float x, bool pos) {
    float em = __expf(-fabsf(x));
    float L  = __logf(1.f + em);
    float sp = fmaxf(x, 0.f) + L;                 // softplus(x)
    float r  = __fdividef(1.f, 1.f + em);
    float s  = (x >= 0.f) ? r : 1.f - r;          // sigmoid(x)
    float bce = sp - (pos ? x : 0.f);
    float om  = pos ? (1.f - s) : s;              // 1 - pt
    return 0.25f * om * om * bce;
}

__global__ __launch_bounds__(BLK)
void k_all(const float* __restrict__ cls4, const float* __restrict__ reg4,
           const float* __restrict__ cls5, const float* __restrict__ reg5,
           const int*   __restrict__ t4c,  const float* __restrict__ t4b,
           const float* __restrict__ t4m,
           const int*   __restrict__ t5c,  const float* __restrict__ t5b,
           const float* __restrict__ t5m,
           float* __restrict__ out)
{
    __shared__ float sacc[8];
    __shared__ int   shit[2];
    __shared__ float sfsum[4];     // per-pair focal accumulator
    __shared__ bool  isLast;

    const int tid  = threadIdx.x;
    const int lane = tid & 31;
    const int l64  = tid & 63;     // lane within the 2-warp pair
    const int pair = tid >> 6;     // 0..3
    const int sw   = (tid >> 5) & 1;
    if (tid < 8) sacc[tid] = 0.f;
    if (tid < 2) shit[tid] = 0;
    if (tid < 4) sfsum[tid] = 0.f;
    __syncthreads();

    const uint32_t tag = g_epoch + 1u;

    // ========== stage 1: issue background float4 load (<=1/thread) ==========
    const int t = blockIdx.x * BLK + tid;
    float4 bgv = make_float4(0.f, 0.f, 0.f, 0.f);
    int bsc = -1;
    if (t < N4Q) {
        int b = t / (HW4/4), c = t - b * (HW4/4);
        bgv = *reinterpret_cast<const float4*>(
            cls4 + (size_t)b * (NCLS+1) * HW4 + (size_t)c * 4);
        bsc = 0;
    } else if (t < N4Q + N5Q) {
        int q = t - N4Q;
        int b = q / (HW5/4), c = q - b * (HW5/4);
        bgv = *reinterpret_cast<const float4*>(
            cls5 + (size_t)b * (NCLS+1) * HW5 + (size_t)c * 4);
        bsc = 1;
    }

    // ========== stage 2: issue per-target box/mask/cid loads ================
    const int w     = blockIdx.x * 4 + pair;      // 0..4095, always valid
    const int scale = (w >= NT) ? 1 : 0;
    const int idx   = w - (scale << 11);
    const int b     = idx >> 6;

    const float* cls;
    const float* reg;
    uint32_t*    map;
    int S, HW;
    float4 tbv;
    float  mask;
    int    cid;
    if (scale) {
        cls = cls5; reg = reg5; map = g_map5; S = 40; HW = HW5;
        tbv  = *reinterpret_cast<const float4*>(t5b + (size_t)idx * 4);
        mask = t5m[idx];  cid = t5c[idx];
    } else {
        cls = cls4; reg = reg4; map = g_map4; S = 80; HW = HW4;
        tbv  = *reinterpret_cast<const float4*>(t4b + (size_t)idx * 4);
        mask = t4m[idx];  cid = t4c[idx];
    }

    // ========== stage 3: consume bg while box loads fly =====================
    {
        float bs = (bsc >= 0)
            ? softplus_fast(bgv.x) + softplus_fast(bgv.y)
            + softplus_fast(bgv.z) + softplus_fast(bgv.w)
            : 0.f;
        #pragma unroll
        for (int o = 16; o; o >>= 1) bs += __shfl_xor_sync(0xffffffffu, bs, o);
        if (lane == 0 && bsc >= 0) atomicAdd(&sacc[4 + bsc], bs);
    }

    // ========== stage 4: gather wave (2 loads/lane over 64 lanes) ===========
    float tx = tbv.x * (float)S, ty = tbv.y * (float)S;
    float tw = tbv.z * (float)S, th = tbv.w * (float)S;
    int gx = (int)fminf(fmaxf(tx, 0.f), (float)(S-1));
    int gy = (int)fminf(fmaxf(ty, 0.f), (float)(S-1));
    int cell = gy * S + gx;

    const float* cbase = cls + (size_t)b * (NCLS+1) * HW + cell;
    const float* rbase = reg + (size_t)b * 4 * HW + cell;

    // load 1: class l64 (0..63)
    float x0 = cbase[(size_t)(1 + l64) * HW];
    // load 2 (sub-warp 0 only): classes 64..79, obj, reg0..3
    float x1 = 0.f;
    if (l64 < 21) {
        const float* p1;
        if      (l64 < 16)  p1 = cbase + (size_t)(65 + l64) * HW;  // class 64+l
        else if (l64 == 16) p1 = cbase;                            // obj logit
        else                p1 = rbase + (size_t)(l64 - 17) * HW;  // reg 0..3
        x1 = *p1;
    }

    // focal math
    float fsum = focal1(x0, l64 == cid);
    if (l64 < 16) fsum += focal1(x1, l64 + 64 == cid);
    #pragma unroll
    for (int o = 16; o; o >>= 1) fsum += __shfl_xor_sync(0xffffffffu, fsum, o);
    if (lane == 0) atomicAdd(&sfsum[pair], fsum);

    // aux values live in sub-warp 0 lanes 16..20
    float obj_t = 0.f, rv0 = 0.f, rv1 = 0.f, rv2 = 0.f, rv3 = 0.f;
    if (sw == 0) {
        obj_t = __shfl_sync(0xffffffffu, x1, 16);
        rv0   = __shfl_sync(0xffffffffu, x1, 17);
        rv1   = __shfl_sync(0xffffffffu, x1, 18);
        rv2   = __shfl_sync(0xffffffffu, x1, 19);
        rv3   = __shfl_sync(0xffffffffu, x1, 20);
    }

    __syncthreads();   // sfsum complete for all pairs

    if (sw == 0 && lane == 0) {
        float fsum_tot = sfsum[pair];

        float dx = __fdividef(1.f, 1.f + __expf(-rv0));
        float dy = __fdividef(1.f, 1.f + __expf(-rv1));
        float dw = __expf(fminf(fmaxf(rv2, -4.f), 4.f));
        float dh = __expf(fminf(fmaxf(rv3, -4.f), 4.f));
        float px = (float)gx + dx, py = (float)gy + dy;

        float d0 = (px - 0.5f*dw) - (tx - 0.5f*tw);
        float d1 = (py - 0.5f*dh) - (ty - 0.5f*th);
        float d2 = (px + 0.5f*dw) - (tx + 0.5f*tw);
        float d3 = (py + 0.5f*dh) - (ty + 0.5f*th);
        float sl1 = 0.f, a;
        a = fabsf(d0); sl1 += (a < 1.f) ? 0.5f*d0*d0 : a - 0.5f;
        a = fabsf(d1); sl1 += (a < 1.f) ? 0.5f*d1*d1 : a - 0.5f;
        a = fabsf(d2); sl1 += (a < 1.f) ? 0.5f*d2*d2 : a - 0.5f;
        a = fabsf(d3); sl1 += (a < 1.f) ? 0.5f*d3*d3 : a - 0.5f;
        sl1 *= 0.25f;

        float em = __expf(-fabsf(obj_t));
        float L  = __logf(1.f + em);
        float sp_neg = fmaxf(-obj_t, 0.f) + L;   // softplus(-obj)
        float sp_pos = fmaxf( obj_t, 0.f) + L;   // softplus(+obj)

        atomicAdd(&sacc[0], sl1 * mask);
        atomicAdd(&sacc[1], sp_neg * mask);
        atomicAdd(&sacc[2], (fsum_tot * (1.f / (float)NCLS)) * mask);
        atomicAdd(&sacc[3], mask);

        if (mask > 0.f) {
            int gidx = b * HW + cell;
            uint32_t old = atomicExch(&map[gidx], tag);
            if (old != tag) {                    // first hit this replay
                atomicAdd(&sacc[6 + scale], sp_pos);
                atomicAdd(&shit[scale], 1);
            }
        }
    }

    // ========== block -> global, last-block finalize ========================
    __syncthreads();
    if (tid < 8) atomicAdd(&g_accf[tid], sacc[tid]);
    if (tid < 2 && shit[tid]) atomicAdd(&g_hit[tid], shit[tid]);

    __threadfence();
    __syncthreads();
    if (tid == 0) {
        unsigned old = atomicAdd(&g_done, 1u);
        isLast = (old == (unsigned)(GRID - 1));
    }
    __syncthreads();
    if (!isLast) return;

    if (tid == 0) {
        volatile float* vf = g_accf;
        volatile int*   vh = g_hit;

        float lb   = vf[0];
        float lo   = vf[1];
        float lc   = vf[2];
        float n    = vf[3];
        float bgs4 = vf[4] - vf[6];
        float bgs5 = vf[5] - vf[7];
        int   bgc4 = BB * HW4 - vh[0];
        int   bgc5 = BB * HW5 - vh[1];

        lo += 0.05f * ((bgc4 > 0) ? bgs4 / (float)(bgc4 > 1 ? bgc4 : 1) : 0.f);
        lo += 0.05f * ((bgc5 > 0) ? bgs5 / (float)(bgc5 > 1 ? bgc5 : 1) : 0.f);

        if (n > 0.f) {
            float dn = fmaxf(n, 1.f);
            lb /= dn;
            lc /= dn;
        }
        lo /= fmaxf(n, 1.f);

        out[0] = 2.0f * lb + 1.0f * lo + 0.5f * lc;

        // reset for next replay (maps persist; epoch bump invalidates them)
        #pragma unroll
        for (int i = 0; i < 8; i++) g_accf[i] = 0.f;
        g_hit[0] = 0; g_hit[1] = 0;
        g_done = 0u;
        g_epoch = tag;
    }
}

extern "C" void kernel_launch(void* const* d_in, const int* in_sizes, int n_in,
                              void* d_out, int out_size)
{
    const float* cls4 = (const float*)d_in[0];
    const float* reg4 = (const float*)d_in[1];
    const float* cls5 = (const float*)d_in[2];
    const float* reg5 = (const float*)d_in[3];
    const int*   t4c  = (const int*)  d_in[4];
    const float* t4b  = (const float*)d_in[5];
    const float* t4m  = (const float*)d_in[6];
    const int*   t5c  = (const int*)  d_in[7];
    const float* t5b  = (const float*)d_in[8];
    const float* t5m  = (const float*)d_in[9];
    float* out = (float*)d_out;

    k_all<<<GRID, BLK>>>(cls4, reg4, cls5, reg5,
                         t4c, t4b, t4m, t5c, t5b, t5m, out);
}

// round 12
// speedup vs baseline: 1.1254x; 1.1254x over previous
#include <cuda_runtime.h>
#include <cuda_bf16.h>
#include <math.h>
#include <stdint.h>

#define NCLS 80
#define BB   32
#define TT   64
#define HW4  (80*80)
#define HW5  (40*40)
#define NT   (BB*TT)          // 2048 targets per scale; 4096 total
#define GRID 512
#define BLK  128              // 4 warps/block, 2 targets per warp
#define N4Q  (BB*HW4/4)       // 51200 float4 quads, scale 4
#define N5Q  (BB*HW5/4)       // 12800 quads, scale 5

// ---- persistent device scratch (zero at load; epoch scheme avoids cleanup) ----
__device__ uint32_t g_map4[BB*HW4];
__device__ uint32_t g_map5[BB*HW5];
// 0 lb, 1 lo, 2 lc, 3 n, 4 tot4, 5 tot5, 6 corr4, 7 corr5
__device__ float    g_accf[8];
__device__ int      g_hit[2];
__device__ unsigned g_done;
__device__ uint32_t g_epoch;

__device__ __forceinline__ float softplus_fast(float x) {
    float em = __expf(-fabsf(x));
    return fmaxf(x, 0.f) + __logf(1.f + em);
}

__device__ __forceinline__ float focal1(float x, bool pos) {
    float em = __expf(-fabsf(x));
    float L  = __logf(1.f + em);
    float sp = fmaxf(x, 0.f) + L;                 // softplus(x)
    float r  = __fdividef(1.f, 1.f + em);
    float s  = (x >= 0.f) ? r : 1.f - r;          // sigmoid(x)
    float bce = sp - (pos ? x : 0.f);
    float om  = pos ? (1.f - s) : s;              // 1 - pt
    return 0.25f * om * om * bce;
}

__global__ __launch_bounds__(BLK)
void k_all(const float* __restrict__ cls4, const float* __restrict__ reg4,
           const float* __restrict__ cls5, const float* __restrict__ reg5,
           const int*   __restrict__ t4c,  const float* __restrict__ t4b,
           const float* __restrict__ t4m,
           const int*   __restrict__ t5c,  const float* __restrict__ t5b,
           const float* __restrict__ t5m,
           float* __restrict__ out)
{
    __shared__ float sacc[8];
    __shared__ int   shit[2];
    __shared__ bool  isLast;

    const int tid  = threadIdx.x;
    const int lane = tid & 31;
    if (tid < 8) sacc[tid] = 0.f;
    if (tid < 2) shit[tid] = 0;
    __syncthreads();

    const uint32_t tag = g_epoch + 1u;

    // ========== stage 1: issue background float4 load (<=1/thread) ==========
    const int t = blockIdx.x * BLK + tid;
    float4 bgv = make_float4(0.f, 0.f, 0.f, 0.f);
    int bsc = -1;
    if (t < N4Q) {
        int b = t / (HW4/4), c = t - b * (HW4/4);
        bgv = *reinterpret_cast<const float4*>(
            cls4 + (size_t)b * (NCLS+1) * HW4 + (size_t)c * 4);
        bsc = 0;
    } else if (t < N4Q + N5Q) {
        int q = t - N4Q;
        int b = q / (HW5/4), c = q - b * (HW5/4);
        bgv = *reinterpret_cast<const float4*>(
            cls5 + (size_t)b * (NCLS+1) * HW5 + (size_t)c * 4);
        bsc = 1;
    }

    // ========== stage 2: this warp owns targets t0 = 2*gw and t0+1 ==========
    const int gw    = blockIdx.x * (BLK >> 5) + (tid >> 5);  // 0..2047
    const int t0    = gw << 1;                               // even target
    const int scale = (t0 >= NT) ? 1 : 0;                    // pair shares scale
    const int idx0  = t0 - (scale << 11);
    const int idx1  = idx0 + 1;
    const int b0    = idx0 >> 6;
    const int b1    = idx1 >> 6;

    const float* cls;
    const float* reg;
    uint32_t*    map;
    int S, HW;
    float4 tbv0, tbv1;
    float  mask0, mask1;
    int    cid0, cid1;
    if (scale) {
        cls = cls5; reg = reg5; map = g_map5; S = 40; HW = HW5;
        tbv0 = *reinterpret_cast<const float4*>(t5b + (size_t)idx0 * 4);
        tbv1 = *reinterpret_cast<const float4*>(t5b + (size_t)idx1 * 4);
        mask0 = t5m[idx0]; mask1 = t5m[idx1];
        cid0  = t5c[idx0]; cid1  = t5c[idx1];
    } else {
        cls = cls4; reg = reg4; map = g_map4; S = 80; HW = HW4;
        tbv0 = *reinterpret_cast<const float4*>(t4b + (size_t)idx0 * 4);
        tbv1 = *reinterpret_cast<const float4*>(t4b + (size_t)idx1 * 4);
        mask0 = t4m[idx0]; mask1 = t4m[idx1];
        cid0  = t4c[idx0]; cid1  = t4c[idx1];
    }

    // ========== stage 3: consume bg while box loads fly =====================
    {
        float bs = (bsc >= 0)
            ? softplus_fast(bgv.x) + softplus_fast(bgv.y)
            + softplus_fast(bgv.z) + softplus_fast(bgv.w)
            : 0.f;
        #pragma unroll
        for (int o = 16; o; o >>= 1) bs += __shfl_xor_sync(0xffffffffu, bs, o);
        if (lane == 0 && bsc >= 0) atomicAdd(&sacc[4 + bsc], bs);
    }

    // ========== stage 4: dual gather wave (4 loads/lane max) ================
    float tx0 = tbv0.x * (float)S, ty0 = tbv0.y * (float)S;
    float tw0 = tbv0.z * (float)S, th0 = tbv0.w * (float)S;
    float tx1 = tbv1.x * (float)S, ty1 = tbv1.y * (float)S;
    float tw1 = tbv1.z * (float)S, th1 = tbv1.w * (float)S;
    int gx0 = (int)fminf(fmaxf(tx0, 0.f), (float)(S-1));
    int gy0 = (int)fminf(fmaxf(ty0, 0.f), (float)(S-1));
    int gx1 = (int)fminf(fmaxf(tx1, 0.f), (float)(S-1));
    int gy1 = (int)fminf(fmaxf(ty1, 0.f), (float)(S-1));
    int cell0 = gy0 * S + gx0;
    int cell1 = gy1 * S + gx1;

    const float* cbase0 = cls + (size_t)b0 * (NCLS+1) * HW + cell0;
    const float* rbase0 = reg + (size_t)b0 * 4 * HW + cell0;
    const float* cbase1 = cls + (size_t)b1 * (NCLS+1) * HW + cell1;
    const float* rbase1 = reg + (size_t)b1 * 4 * HW + cell1;

    // aux pointer pattern: lanes 0..15 -> class 65+lane, 16 -> obj, 17..20 -> reg
    const float* p0b;
    const float* p1b;
    if      (lane < 16)  { p0b = cbase0 + (size_t)(65 + lane) * HW;
                           p1b = cbase1 + (size_t)(65 + lane) * HW; }
    else if (lane == 16) { p0b = cbase0;  p1b = cbase1; }
    else if (lane <= 20) { p0b = rbase0 + (size_t)(lane - 17) * HW;
                           p1b = rbase1 + (size_t)(lane - 17) * HW; }
    else                 { p0b = cbase0;  p1b = cbase1; }   // broadcast dup of obj

    // issue all 4 gather loads back-to-back (max MLP)
    float x0a = cbase0[(size_t)(1 + lane) * HW];
    float x1a = cbase1[(size_t)(1 + lane) * HW];
    float x0b = *p0b;
    float x1b = *p1b;

    // focal math, both targets interleaved
    float f0 = focal1(x0a, lane == cid0);
    float f1 = focal1(x1a, lane == cid1);
    if (lane < 16) {
        f0 += focal1(x0b, lane + 64 == cid0);
        f1 += focal1(x1b, lane + 64 == cid1);
    }
    #pragma unroll
    for (int o = 16; o; o >>= 1) {
        f0 += __shfl_xor_sync(0xffffffffu, f0, o);
        f1 += __shfl_xor_sync(0xffffffffu, f1, o);
    }

    // aux values from lanes 16..20 (delivered to all lanes)
    float obj0 = __shfl_sync(0xffffffffu, x0b, 16);
    float ra0  = __shfl_sync(0xffffffffu, x0b, 17);
    float rb0  = __shfl_sync(0xffffffffu, x0b, 18);
    float rc0  = __shfl_sync(0xffffffffu, x0b, 19);
    float rd0  = __shfl_sync(0xffffffffu, x0b, 20);
    float obj1 = __shfl_sync(0xffffffffu, x1b, 16);
    float ra1  = __shfl_sync(0xffffffffu, x1b, 17);
    float rb1  = __shfl_sync(0xffffffffu, x1b, 18);
    float rc1  = __shfl_sync(0xffffffffu, x1b, 19);
    float rd1  = __shfl_sync(0xffffffffu, x1b, 20);

    // epilogue: lane 0 handles target0, lane 1 handles target1 (in parallel)
    if (lane < 2) {
        bool  one  = (lane == 1);
        float fsum = one ? f1   : f0;
        float objt = one ? obj1 : obj0;
        float rv0  = one ? ra1  : ra0;
        float rv1  = one ? rb1  : rb0;
        float rv2  = one ? rc1  : rc0;
        float rv3  = one ? rd1  : rd0;
        float tx   = one ? tx1  : tx0,  ty = one ? ty1 : ty0;
        float tw   = one ? tw1  : tw0,  th = one ? th1 : th0;
        int   gx   = one ? gx1  : gx0,  gy = one ? gy1 : gy0;
        int   cell = one ? cell1 : cell0;
        int   b    = one ? b1   : b0;
        float mask = one ? mask1 : mask0;

        float dx = __fdividef(1.f, 1.f + __expf(-rv0));
        float dy = __fdividef(1.f, 1.f + __expf(-rv1));
        float dw = __expf(fminf(fmaxf(rv2, -4.f), 4.f));
        float dh = __expf(fminf(fmaxf(rv3, -4.f), 4.f));
        float px = (float)gx + dx, py = (float)gy + dy;

        float d0 = (px - 0.5f*dw) - (tx - 0.5f*tw);
        float d1 = (py - 0.5f*dh) - (ty - 0.5f*th);
        float d2 = (px + 0.5f*dw) - (tx + 0.5f*tw);
        float d3 = (py + 0.5f*dh) - (ty + 0.5f*th);
        float sl1 = 0.f, a;
        a = fabsf(d0); sl1 += (a < 1.f) ? 0.5f*d0*d0 : a - 0.5f;
        a = fabsf(d1); sl1 += (a < 1.f) ? 0.5f*d1*d1 : a - 0.5f;
        a = fabsf(d2); sl1 += (a < 1.f) ? 0.5f*d2*d2 : a - 0.5f;
        a = fabsf(d3); sl1 += (a < 1.f) ? 0.5f*d3*d3 : a - 0.5f;
        sl1 *= 0.25f;

        float em = __expf(-fabsf(objt));
        float L  = __logf(1.f + em);
        float sp_neg = fmaxf(-objt, 0.f) + L;   // softplus(-obj)
        float sp_pos = fmaxf( objt, 0.f) + L;   // softplus(+obj)

        atomicAdd(&sacc[0], sl1 * mask);
        atomicAdd(&sacc[1], sp_neg * mask);
        atomicAdd(&sacc[2], (fsum * (1.f / (float)NCLS)) * mask);
        atomicAdd(&sacc[3], mask);

        if (mask > 0.f) {
            int gidx = b * HW + cell;
            uint32_t old = atomicExch(&map[gidx], tag);
            if (old != tag) {                    // first hit this replay
                atomicAdd(&sacc[6 + scale], sp_pos);
                atomicAdd(&shit[scale], 1);
            }
        }
    }

    // ========== block -> global, last-block finalize ========================
    __syncthreads();
    if (tid < 8) atomicAdd(&g_accf[tid], sacc[tid]);
    if (tid < 2 && shit[tid]) atomicAdd(&g_hit[tid], shit[tid]);

    __threadfence();
    __syncthreads();
    if (tid == 0) {
        unsigned old = atomicAdd(&g_done, 1u);
        isLast = (old == (unsigned)(GRID - 1));
    }
    __syncthreads();
    if (!isLast) return;

    if (tid == 0) {
        volatile float* vf = g_accf;
        volatile int*   vh = g_hit;

        float lb   = vf[0];
        float lo   = vf[1];
        float lc   = vf[2];
        float n    = vf[3];
        float bgs4 = vf[4] - vf[6];
        float bgs5 = vf[5] - vf[7];
        int   bgc4 = BB * HW4 - vh[0];
        int   bgc5 = BB * HW5 - vh[1];

        lo += 0.05f * ((bgc4 > 0) ? bgs4 / (float)(bgc4 > 1 ? bgc4 : 1) : 0.f);
        lo += 0.05f * ((bgc5 > 0) ? bgs5 / (float)(bgc5 > 1 ? bgc5 : 1) : 0.f);

        if (n > 0.f) {
            float dn = fmaxf(n, 1.f);
            lb /= dn;
            lc /= dn;
        }
        lo /= fmaxf(n, 1.f);

        out[0] = 2.0f * lb + 1.0f * lo + 0.5f * lc;

        // reset for next replay (maps persist; epoch bump invalidates them)
        #pragma unroll
        for (int i = 0; i < 8; i++) g_accf[i] = 0.f;
        g_hit[0] = 0; g_hit[1] = 0;
        g_done = 0u;
        g_epoch = tag;
    }
}

extern "C" void kernel_launch(void* const* d_in, const int* in_sizes, int n_in,
                              void* d_out, int out_size)
{
    const float* cls4 = (const float*)d_in[0];
    const float* reg4 = (const float*)d_in[1];
    const float* cls5 = (const float*)d_in[2];
    const float* reg5 = (const float*)d_in[3];
    const int*   t4c  = (const int*)  d_in[4];
    const float* t4b  = (const float*)d_in[5];
    const float* t4m  = (const float*)d_in[6];
    const int*   t5c  = (const int*)  d_in[7];
    const float* t5b  = (const float*)d_in[8];
    const float* t5m  = (const float*)d_in[9];
    float* out = (float*)d_out;

    k_all<<<GRID, BLK>>>(cls4, reg4, cls5, reg5,
                         t4c, t4b, t4m, t5c, t5b, t5m, out);
}

// round 14
// speedup vs baseline: 1.1488x; 1.0208x over previous
#include <cuda_runtime.h>
#include <cuda_bf16.h>
#include <math.h>
#include <stdint.h>

#define NCLS 80
#define BB   32
#define TT   64
#define HW4  (80*80)
#define HW5  (40*40)
#define NT   (BB*TT)          // 2048 targets per scale; 4096 total
#define GRID 512
#define BLK  128              // 4 warps/block, 2 targets per warp
#define N4Q  (BB*HW4/4)       // 51200 float4 quads, scale 4
#define N5Q  (BB*HW5/4)       // 12800 quads, scale 5

// ---- persistent device scratch (zero at load; epoch scheme avoids cleanup) ----
__device__ uint32_t g_map4[BB*HW4];
__device__ uint32_t g_map5[BB*HW5];
// 0 lb, 1 lo, 2 lc, 3 n, 4 tot4, 5 tot5, 6 corr4, 7 corr5
__device__ float    g_accf[8];
__device__ int      g_hit[2];
__device__ unsigned g_done;
__device__ uint32_t g_epoch;

__device__ __forceinline__ float softplus_fast(float x) {
    float em = __expf(-fabsf(x));
    return fmaxf(x, 0.f) + __logf(1.f + em);
}

__device__ __forceinline__ float focal1(float x, bool pos) {
    float em = __expf(-fabsf(x));
    float L  = __logf(1.f + em);
    float sp = fmaxf(x, 0.f) + L;                 // softplus(x)
    float r  = __fdividef(1.f, 1.f + em);
    float s  = (x >= 0.f) ? r : 1.f - r;          // sigmoid(x)
    float bce = sp - (pos ? x : 0.f);
    float om  = pos ? (1.f - s) : s;              // 1 - pt
    return 0.25f * om * om * bce;
}

__global__ __launch_bounds__(BLK)
void k_all(const float* __restrict__ cls4, const float* __restrict__ reg4,
           const float* __restrict__ cls5, const float* __restrict__ reg5,
           const int*   __restrict__ t4c,  const float* __restrict__ t4b,
           const float* __restrict__ t4m,
           const int*   __restrict__ t5c,  const float* __restrict__ t5b,
           const float* __restrict__ t5m,
           float* __restrict__ out)
{
    __shared__ float sacc[8];
    __shared__ int   shit[2];
    __shared__ bool  isLast;

    const int tid  = threadIdx.x;
    const int lane = tid & 31;
    if (tid < 8) sacc[tid] = 0.f;
    if (tid < 2) shit[tid] = 0;
    __syncthreads();

    const uint32_t tag = g_epoch + 1u;

    // ========== stage 1: issue background float4 load (<=1/thread) ==========
    const int t = blockIdx.x * BLK + tid;
    float4 bgv = make_float4(0.f, 0.f, 0.f, 0.f);
    int bsc = -1;
    if (t < N4Q) {
        int b = t / (HW4/4), c = t - b * (HW4/4);
        bgv = *reinterpret_cast<const float4*>(
            cls4 + (size_t)b * (NCLS+1) * HW4 + (size_t)c * 4);
        bsc = 0;
    } else if (t < N4Q + N5Q) {
        int q = t - N4Q;
        int b = q / (HW5/4), c = q - b * (HW5/4);
        bgv = *reinterpret_cast<const float4*>(
            cls5 + (size_t)b * (NCLS+1) * HW5 + (size_t)c * 4);
        bsc = 1;
    }

    // ========== stage 2: this warp owns targets t0 = 2*gw and t0+1 ==========
    const int gw    = blockIdx.x * (BLK >> 5) + (tid >> 5);  // 0..2047
    const int t0    = gw << 1;                               // even target
    const int scale = (t0 >= NT) ? 1 : 0;                    // pair shares scale
    const int idx0  = t0 - (scale << 11);
    const int idx1  = idx0 + 1;
    const int b0    = idx0 >> 6;
    const int b1    = idx1 >> 6;

    const float* cls;
    const float* reg;
    uint32_t*    map;
    int S, HW;
    float4 tbv0, tbv1;
    float  mask0, mask1;
    int    cid0, cid1;
    if (scale) {
        cls = cls5; reg = reg5; map = g_map5; S = 40; HW = HW5;
        tbv0 = *reinterpret_cast<const float4*>(t5b + (size_t)idx0 * 4);
        tbv1 = *reinterpret_cast<const float4*>(t5b + (size_t)idx1 * 4);
        mask0 = t5m[idx0]; mask1 = t5m[idx1];
        cid0  = t5c[idx0]; cid1  = t5c[idx1];
    } else {
        cls = cls4; reg = reg4; map = g_map4; S = 80; HW = HW4;
        tbv0 = *reinterpret_cast<const float4*>(t4b + (size_t)idx0 * 4);
        tbv1 = *reinterpret_cast<const float4*>(t4b + (size_t)idx1 * 4);
        mask0 = t4m[idx0]; mask1 = t4m[idx1];
        cid0  = t4c[idx0]; cid1  = t4c[idx1];
    }

    // ========== stage 3: consume bg while box loads fly =====================
    {
        float bs = (bsc >= 0)
            ? softplus_fast(bgv.x) + softplus_fast(bgv.y)
            + softplus_fast(bgv.z) + softplus_fast(bgv.w)
            : 0.f;
        #pragma unroll
        for (int o = 16; o; o >>= 1) bs += __shfl_xor_sync(0xffffffffu, bs, o);
        if (lane == 0 && bsc >= 0) atomicAdd(&sacc[4 + bsc], bs);
    }

    // ========== stage 4: dual FULL gather wave (6 loads/lane) ===============
    float tx0 = tbv0.x * (float)S, ty0 = tbv0.y * (float)S;
    float tw0 = tbv0.z * (float)S, th0 = tbv0.w * (float)S;
    float tx1 = tbv1.x * (float)S, ty1 = tbv1.y * (float)S;
    float tw1 = tbv1.z * (float)S, th1 = tbv1.w * (float)S;
    int gx0 = (int)fminf(fmaxf(tx0, 0.f), (float)(S-1));
    int gy0 = (int)fminf(fmaxf(ty0, 0.f), (float)(S-1));
    int gx1 = (int)fminf(fmaxf(tx1, 0.f), (float)(S-1));
    int gy1 = (int)fminf(fmaxf(ty1, 0.f), (float)(S-1));
    int cell0 = gy0 * S + gx0;
    int cell1 = gy1 * S + gx1;

    const float* cbase0 = cls + (size_t)b0 * (NCLS+1) * HW + cell0;
    const float* rbase0 = reg + (size_t)b0 * 4 * HW + cell0;
    const float* cbase1 = cls + (size_t)b1 * (NCLS+1) * HW + cell1;
    const float* rbase1 = reg + (size_t)b1 * 4 * HW + cell1;

    // aux pointer pattern: lanes 0..15 -> class 64+lane, 16 -> obj, 17..20 -> reg
    const float* p0b;
    const float* p1b;
    if      (lane < 16)  { p0b = cbase0 + (size_t)(65 + lane) * HW;
                           p1b = cbase1 + (size_t)(65 + lane) * HW; }
    else if (lane == 16) { p0b = cbase0;  p1b = cbase1; }
    else if (lane <= 20) { p0b = rbase0 + (size_t)(lane - 17) * HW;
                           p1b = rbase1 + (size_t)(lane - 17) * HW; }
    else                 { p0b = cbase0;  p1b = cbase1; }   // broadcast dup of obj

    // issue all 6 gather loads back-to-back (max front-batched MLP)
    float x0a = cbase0[(size_t)(1 + lane)  * HW];   // classes  0..31
    float x0c = cbase0[(size_t)(33 + lane) * HW];   // classes 32..63
    float x1a = cbase1[(size_t)(1 + lane)  * HW];
    float x1c = cbase1[(size_t)(33 + lane) * HW];
    float x0b = *p0b;                               // classes 64..79 + obj + reg
    float x1b = *p1b;

    // focal math, both targets interleaved
    float f0 = focal1(x0a, lane == cid0) + focal1(x0c, lane + 32 == cid0);
    float f1 = focal1(x1a, lane == cid1) + focal1(x1c, lane + 32 == cid1);
    if (lane < 16) {
        f0 += focal1(x0b, lane + 64 == cid0);
        f1 += focal1(x1b, lane + 64 == cid1);
    }
    #pragma unroll
    for (int o = 16; o; o >>= 1) {
        f0 += __shfl_xor_sync(0xffffffffu, f0, o);
        f1 += __shfl_xor_sync(0xffffffffu, f1, o);
    }

    // aux values from lanes 16..20 (delivered to all lanes)
    float obj0 = __shfl_sync(0xffffffffu, x0b, 16);
    float ra0  = __shfl_sync(0xffffffffu, x0b, 17);
    float rb0  = __shfl_sync(0xffffffffu, x0b, 18);
    float rc0  = __shfl_sync(0xffffffffu, x0b, 19);
    float rd0  = __shfl_sync(0xffffffffu, x0b, 20);
    float obj1 = __shfl_sync(0xffffffffu, x1b, 16);
    float ra1  = __shfl_sync(0xffffffffu, x1b, 17);
    float rb1  = __shfl_sync(0xffffffffu, x1b, 18);
    float rc1  = __shfl_sync(0xffffffffu, x1b, 19);
    float rd1  = __shfl_sync(0xffffffffu, x1b, 20);

    // epilogue: lane 0 handles target0, lane 1 handles target1 (in parallel)
    if (lane < 2) {
        bool  one  = (lane == 1);
        float fsum = one ? f1   : f0;
        float objt = one ? obj1 : obj0;
        float rv0  = one ? ra1  : ra0;
        float rv1  = one ? rb1  : rb0;
        float rv2  = one ? rc1  : rc0;
        float rv3  = one ? rd1  : rd0;
        float tx   = one ? tx1  : tx0,  ty = one ? ty1 : ty0;
        float tw   = one ? tw1  : tw0,  th = one ? th1 : th0;
        int   gx   = one ? gx1  : gx0,  gy = one ? gy1 : gy0;
        int   cell = one ? cell1 : cell0;
        int   b    = one ? b1   : b0;
        float mask = one ? mask1 : mask0;

        float dx = __fdividef(1.f, 1.f + __expf(-rv0));
        float dy = __fdividef(1.f, 1.f + __expf(-rv1));
        float dw = __expf(fminf(fmaxf(rv2, -4.f), 4.f));
        float dh = __expf(fminf(fmaxf(rv3, -4.f), 4.f));
        float px = (float)gx + dx, py = (float)gy + dy;

        float d0 = (px - 0.5f*dw) - (tx - 0.5f*tw);
        float d1 = (py - 0.5f*dh) - (ty - 0.5f*th);
        float d2 = (px + 0.5f*dw) - (tx + 0.5f*tw);
        float d3 = (py + 0.5f*dh) - (ty + 0.5f*th);
        float sl1 = 0.f, a;
        a = fabsf(d0); sl1 += (a < 1.f) ? 0.5f*d0*d0 : a - 0.5f;
        a = fabsf(d1); sl1 += (a < 1.f) ? 0.5f*d1*d1 : a - 0.5f;
        a = fabsf(d2); sl1 += (a < 1.f) ? 0.5f*d2*d2 : a - 0.5f;
        a = fabsf(d3); sl1 += (a < 1.f) ? 0.5f*d3*d3 : a - 0.5f;
        sl1 *= 0.25f;

        float em = __expf(-fabsf(objt));
        float L  = __logf(1.f + em);
        float sp_neg = fmaxf(-objt, 0.f) + L;   // softplus(-obj)
        float sp_pos = fmaxf( objt, 0.f) + L;   // softplus(+obj)

        atomicAdd(&sacc[0], sl1 * mask);
        atomicAdd(&sacc[1], sp_neg * mask);
        atomicAdd(&sacc[2], (fsum * (1.f / (float)NCLS)) * mask);
        atomicAdd(&sacc[3], mask);

        if (mask > 0.f) {
            int gidx = b * HW + cell;
            uint32_t old = atomicExch(&map[gidx], tag);
            if (old != tag) {                    // first hit this replay
                atomicAdd(&sacc[6 + scale], sp_pos);
                atomicAdd(&shit[scale], 1);
            }
        }
    }

    // ========== block -> global, last-block finalize ========================
    __syncthreads();
    if (tid < 8) atomicAdd(&g_accf[tid], sacc[tid]);
    if (tid < 2 && shit[tid]) atomicAdd(&g_hit[tid], shit[tid]);

    __threadfence();
    __syncthreads();
    if (tid == 0) {
        unsigned old = atomicAdd(&g_done, 1u);
        isLast = (old == (unsigned)(GRID - 1));
    }
    __syncthreads();
    if (!isLast) return;

    if (tid == 0) {
        volatile float* vf = g_accf;
        volatile int*   vh = g_hit;

        float lb   = vf[0];
        float lo   = vf[1];
        float lc   = vf[2];
        float n    = vf[3];
        float bgs4 = vf[4] - vf[6];
        float bgs5 = vf[5] - vf[7];
        int   bgc4 = BB * HW4 - vh[0];
        int   bgc5 = BB * HW5 - vh[1];

        lo += 0.05f * ((bgc4 > 0) ? bgs4 / (float)(bgc4 > 1 ? bgc4 : 1) : 0.f);
        lo += 0.05f * ((bgc5 > 0) ? bgs5 / (float)(bgc5 > 1 ? bgc5 : 1) : 0.f);

        if (n > 0.f) {
            float dn = fmaxf(n, 1.f);
            lb /= dn;
            lc /= dn;
        }
        lo /= fmaxf(n, 1.f);

        out[0] = 2.0f * lb + 1.0f * lo + 0.5f * lc;

        // reset for next replay (maps persist; epoch bump invalidates them)
        #pragma unroll
        for (int i = 0; i < 8; i++) g_accf[i] = 0.f;
        g_hit[0] = 0; g_hit[1] = 0;
        g_done = 0u;
        g_epoch = tag;
    }
}

extern "C" void kernel_launch(void* const* d_in, const int* in_sizes, int n_in,
                              void* d_out, int out_size)
{
    const float* cls4 = (const float*)d_in[0];
    const float* reg4 = (const float*)d_in[1];
    const float* cls5 = (const float*)d_in[2];
    const float* reg5 = (const float*)d_in[3];
    const int*   t4c  = (const int*)  d_in[4];
    const float* t4b  = (const float*)d_in[5];
    const float* t4m  = (const float*)d_in[6];
    const int*   t5c  = (const int*)  d_in[7];
    const float* t5b  = (const float*)d_in[8];
    const float* t5m  = (const float*)d_in[9];
    float* out = (float*)d_out;

    k_all<<<GRID, BLK>>>(cls4, reg4, cls5, reg5,
                         t4c, t4b, t4m, t5c, t5b, t5m, out);
}